// round 6
// baseline (speedup 1.0000x reference)
#include <cuda_runtime.h>
#include <cstdint>
#include <math.h>

#define NPIX 9409
#define LDF  9412          /* padded row stride for f/g; pads stay 0 forever */
#define CIN  512
#define CMIX 1024
#define C1N  256
#define C2N  512
#define BN_INV 0.9999950000374997f

// ------------------------- scratch (static device) --------------------------
__device__ float d_xmixT[NPIX * CMIX];        // [9409, 1024] (tf32-rounded)
__device__ float d_tT  [NPIX * C1N];          // [9409, 256]  (tf32-rounded)
__device__ float d_g   [C2N * LDF];           // [512, 9412]  (tf32-rounded)
__device__ float d_f   [NPIX * LDF];          // [9409, 9412] raw f scores
__device__ float d_yT  [NPIX * C2N];          // [9409, 512]  (tf32-rounded)
__device__ float d_rmax[NPIX];
__device__ float d_rinv[NPIX];
__device__ float d_wtR [C1N * CMIX];          // rounded weights
__device__ float d_wgR [C2N * CMIX];
__device__ float d_woR [CIN * C2N];

// ------------------------- helpers ------------------------------------------
__device__ __forceinline__ uint32_t f2tf(float v) {
    uint32_t u;
    asm("cvt.rna.tf32.f32 %0, %1;" : "=r"(u) : "f"(v));
    return u;
}
__device__ __forceinline__ float rtf(float v) { return __uint_as_float(f2tf(v)); }

__device__ __forceinline__ void mma_tf32(float c[4], uint32_t a0, uint32_t a1,
                                         uint32_t a2, uint32_t a3,
                                         uint32_t b0, uint32_t b1) {
    asm volatile(
        "mma.sync.aligned.m16n8k8.row.col.f32.tf32.tf32.f32 "
        "{%0,%1,%2,%3}, {%4,%5,%6,%7}, {%8,%9}, {%0,%1,%2,%3};"
        : "+f"(c[0]), "+f"(c[1]), "+f"(c[2]), "+f"(c[3])
        : "r"(a0), "r"(a1), "r"(a2), "r"(a3), "r"(b0), "r"(b1));
}

// fast exp on the FMA pipe (no MUFU)
__device__ __forceinline__ float fexp(float x) {
    x = fmaxf(x, -87.0f);
    float t = x * 1.4426950408889634f;
    float fl = floorf(t);
    float f = t - fl;
    float p = 1.52527338e-5f;
    p = fmaf(p, f, 1.54035304e-4f);
    p = fmaf(p, f, 1.33335581e-3f);
    p = fmaf(p, f, 9.61812911e-3f);
    p = fmaf(p, f, 5.55041087e-2f);
    p = fmaf(p, f, 2.40226507e-1f);
    p = fmaf(p, f, 6.93147181e-1f);
    p = fmaf(p, f, 1.0f);
    int i = (int)fl;
    return p * __int_as_float((i + 127) << 23);
}

// ------------------------- small prep kernels -------------------------------
__global__ void round_k(const float* __restrict__ in, float* __restrict__ out, int n) {
    int i = blockIdx.x * 256 + threadIdx.x;
    if (i < n) out[i] = rtf(in[i]);
}

// xmixT[n, k] = tf32round( (k<512) ? x[k, n] : pos[k-512, n] )
__global__ void concatT_k(const float* __restrict__ x, const float* __restrict__ pos) {
    __shared__ float tile[32][33];
    const float* S = blockIdx.z ? pos : x;
    int c0 = blockIdx.y * 32, n0 = blockIdx.x * 32;
    int tx = threadIdx.x, ty = threadIdx.y;
    #pragma unroll
    for (int i = 0; i < 32; i += 8) {
        int c = c0 + ty + i, n = n0 + tx;
        if (n < NPIX) tile[ty + i][tx] = S[(size_t)c * NPIX + n];
    }
    __syncthreads();
    int kbase = blockIdx.z * 512 + c0;
    #pragma unroll
    for (int i = 0; i < 32; i += 8) {
        int n = n0 + ty + i;
        if (n < NPIX) d_xmixT[(size_t)n * CMIX + kbase + tx] = rtf(tile[tx][ty + i]);
    }
}

// ------------------------- mma.sync tf32 GEMM, cp.async pipelined -----------
// D[M,N] = epi( sum_k A'[m,k]*B[n,k] );  A [M,K] lda, B [N,K] ldb, C [M,N] ldc
// EXPA: A'[m,k] = exp(A[m,k] - rmax[m]) (tf32-rounded); else A' = A
// EPI 0: *alpha   1: +p1[gm]   2: relu((acc+p1[gn])*p2[gn]*BN_INV+p3[gn])   3: *p1[gm]
// SYM: M==Nn, A==B; only bx>=by tiles launched; mirror-write transpose tile
#define GEMM_SMEM 73728   /* 2 buffers x (A 18432 + B 18432); >= 66048 staging */

template <int EPI, int ROUND, int EXPA, int SYM>
__global__ void __launch_bounds__(256, 2)
gemm_mma(const float* __restrict__ A, const float* __restrict__ B, float* __restrict__ C,
         int M, int Nn, int K, int lda, int ldb, int ldc,
         const float* __restrict__ p1, const float* __restrict__ p2,
         const float* __restrict__ p3, float alpha,
         const float* __restrict__ rmax) {
    if (SYM && blockIdx.y > blockIdx.x) return;
    extern __shared__ char dsm[];
    float* smf = (float*)dsm;
    const uint32_t sbase = (uint32_t)__cvta_generic_to_shared(dsm);

    const int tid  = threadIdx.x;
    const int lane = tid & 31, wid = tid >> 5;
    const int wm = wid & 1;          // 2 warp rows (64 m each)
    const int wn = wid >> 1;         // 4 warp cols (32 n each)
    const int g   = lane >> 2;       // 0..7
    const int tig = lane & 3;        // 0..3
    const int m0 = blockIdx.y * 128, n0 = blockIdx.x * 128;

    const int lr  = tid >> 3;        // 0..31
    const int kv4 = (tid & 7) << 2;  // 0,4,...,28

    float acc[4][4][4];
    #pragma unroll
    for (int mt = 0; mt < 4; ++mt)
        #pragma unroll
        for (int nt = 0; nt < 4; ++nt)
            #pragma unroll
            for (int c = 0; c < 4; ++c) acc[mt][nt][c] = 0.f;

    const int KT = (K + 31) >> 5;

    // per-thread row constants for EXPA
    float rm4[4];
    if (EXPA) {
        #pragma unroll
        for (int i = 0; i < 4; ++i) {
            int gm = m0 + lr + (i << 5);
            rm4[i] = (gm < M) ? rmax[gm] : 0.f;
        }
    }

    auto issueB = [&](int t) {
        const int gk = (t << 5) + kv4;
        uint32_t sb = sbase + (uint32_t)(t & 1) * 36864u + 18432u;
        #pragma unroll
        for (int i = 0; i < 4; ++i) {
            int row = lr + (i << 5);
            uint32_t off = (uint32_t)(row * 144 + (kv4 << 2));
            const float* pb = B + (size_t)(n0 + row) * ldb + gk;
            int szb = ((n0 + row) < Nn && gk < K) ? 16 : 0;
            if (!szb) pb = B;
            asm volatile("cp.async.cg.shared.global [%0], [%1], 16, %2;"
                         :: "r"(sb + off), "l"(pb), "r"(szb) : "memory");
        }
    };
    auto issueA_async = [&](int t) {
        const int gk = (t << 5) + kv4;
        uint32_t sa = sbase + (uint32_t)(t & 1) * 36864u;
        #pragma unroll
        for (int i = 0; i < 4; ++i) {
            int row = lr + (i << 5);
            uint32_t off = (uint32_t)(row * 144 + (kv4 << 2));
            const float* pa = A + (size_t)(m0 + row) * lda + gk;
            int sza = ((m0 + row) < M && gk < K) ? 16 : 0;
            if (!sza) pa = A;
            asm volatile("cp.async.cg.shared.global [%0], [%1], 16, %2;"
                         :: "r"(sa + off), "l"(pa), "r"(sza) : "memory");
        }
    };
    auto ldgA = [&](int t, float4 ra[4]) {
        const int gk = (t << 5) + kv4;
        #pragma unroll
        for (int i = 0; i < 4; ++i) {
            int gm = m0 + lr + (i << 5);
            ra[i] = make_float4(0.f, 0.f, 0.f, 0.f);
            if (gm < M && gk < K) ra[i] = *(const float4*)(A + (size_t)gm * lda + gk);
        }
    };
    auto stsA_exp = [&](int t, const float4 ra[4]) {
        uint32_t sa = sbase + (uint32_t)(t & 1) * 36864u;
        #pragma unroll
        for (int i = 0; i < 4; ++i) {
            int row = lr + (i << 5);
            uint32_t off = (uint32_t)(row * 144 + (kv4 << 2));
            float ex = rtf(fexp(ra[i].x - rm4[i]));
            float ey = rtf(fexp(ra[i].y - rm4[i]));
            float ez = rtf(fexp(ra[i].z - rm4[i]));
            float ew = rtf(fexp(ra[i].w - rm4[i]));
            asm volatile("st.shared.v4.b32 [%0], {%1, %2, %3, %4};"
                         :: "r"(sa + off), "r"(__float_as_uint(ex)), "r"(__float_as_uint(ey)),
                            "r"(__float_as_uint(ez)), "r"(__float_as_uint(ew)) : "memory");
        }
    };

    float4 ra[4];
    if (EXPA) {
        ldgA(0, ra);
        issueB(0);
        asm volatile("cp.async.commit_group;" ::: "memory");
    } else {
        issueA_async(0);
        issueB(0);
        asm volatile("cp.async.commit_group;" ::: "memory");
    }

    for (int t = 0; t < KT; ++t) {
        if (t + 1 < KT) {
            if (EXPA) {
                issueB(t + 1);
                asm volatile("cp.async.commit_group;" ::: "memory");
            } else {
                issueA_async(t + 1);
                issueB(t + 1);
                asm volatile("cp.async.commit_group;" ::: "memory");
            }
        }
        if (EXPA) {
            stsA_exp(t, ra);
            if (t + 1 < KT) ldgA(t + 1, ra);
        }
        if (t + 1 < KT) asm volatile("cp.async.wait_group 1;" ::: "memory");
        else            asm volatile("cp.async.wait_group 0;" ::: "memory");
        __syncthreads();

        const float* As = smf + (t & 1) * 9216;
        const float* Bs = As + 4608;

        #pragma unroll
        for (int ks = 0; ks < 4; ++ks) {
            const int kk = ks * 8;
            uint32_t bf[4][2];
            #pragma unroll
            for (int nt = 0; nt < 4; ++nt) {
                int col = wn * 32 + nt * 8 + g;
                bf[nt][0] = __float_as_uint(Bs[col * 36 + kk + tig]);
                bf[nt][1] = __float_as_uint(Bs[col * 36 + kk + tig + 4]);
            }
            #pragma unroll
            for (int mt = 0; mt < 4; ++mt) {
                int row = wm * 64 + mt * 16;
                uint32_t a0 = __float_as_uint(As[(row + g    ) * 36 + kk + tig]);
                uint32_t a1 = __float_as_uint(As[(row + g + 8) * 36 + kk + tig]);
                uint32_t a2 = __float_as_uint(As[(row + g    ) * 36 + kk + tig + 4]);
                uint32_t a3 = __float_as_uint(As[(row + g + 8) * 36 + kk + tig + 4]);
                #pragma unroll
                for (int nt = 0; nt < 4; ++nt)
                    mma_tf32(acc[mt][nt], a0, a1, a2, a3, bf[nt][0], bf[nt][1]);
            }
        }
        __syncthreads();
    }

    // ------------------------- epilogue -------------------------
    float* stg = smf;   // SYM: 128x129 staging (66 KB) — mainloop buffers dead now
    #pragma unroll
    for (int mt = 0; mt < 4; ++mt) {
        #pragma unroll
        for (int half = 0; half < 2; ++half) {
            int lm = wm * 64 + mt * 16 + g + half * 8;
            int gm = m0 + lm;
            if (gm >= M) continue;
            float rp = 0.f;
            if (EPI == 1 || EPI == 3) rp = p1[gm];
            float* crow = C + (size_t)gm * ldc;
            #pragma unroll
            for (int nt = 0; nt < 4; ++nt) {
                #pragma unroll
                for (int cc = 0; cc < 2; ++cc) {
                    int ln = wn * 32 + nt * 8 + tig * 2 + cc;
                    int gn = n0 + ln;
                    if (gn < Nn) {
                        float v = acc[mt][nt][half * 2 + cc];
                        if (EPI == 0)      v *= alpha;
                        else if (EPI == 1) v += rp;
                        else if (EPI == 2) v = fmaxf(fmaf(v + p1[gn], p2[gn] * BN_INV, p3[gn]), 0.f);
                        else               v *= rp;
                        if (ROUND) v = rtf(v);
                        crow[gn] = v;
                        if (SYM) stg[ln * 129 + lm] = v;
                    }
                }
            }
        }
    }
    if (SYM && blockIdx.x != blockIdx.y) {
        __syncthreads();
        for (int e = tid; e < 128 * 128; e += 256) {
            int ln = e >> 7, lm = e & 127;
            int gn = n0 + ln, gm = m0 + lm;
            if (gn < Nn && gm < M)
                C[(size_t)gn * ldc + gm] = stg[ln * 129 + lm];
        }
    }
}

// ------------------------- row stats: online max + sumexp -------------------
__global__ void __launch_bounds__(256) rowstats_k() {
    const int row = blockIdx.x;
    const float* p = d_f + (size_t)row * LDF;
    float m = -1e30f, s = 0.f;
    for (int q = threadIdx.x; q < 2352; q += 256) {       // quads cover 0..9407
        float4 v = *(const float4*)(p + (q << 2));
        float lm = fmaxf(fmaxf(v.x, v.y), fmaxf(v.z, v.w));
        if (lm > m) { s *= fexp(m - lm); m = lm; }
        s += fexp(v.x - m) + fexp(v.y - m) + fexp(v.z - m) + fexp(v.w - m);
    }
    if (threadIdx.x == 0) {                                // tail element 9408
        float v = p[9408];
        if (v > m) { s *= fexp(m - v); m = v; }
        s += fexp(v - m);
    }
    __shared__ float sm[256], ss[256];
    sm[threadIdx.x] = m; ss[threadIdx.x] = s;
    __syncthreads();
    for (int off = 128; off > 0; off >>= 1) {
        if (threadIdx.x < off) {
            float m1 = sm[threadIdx.x], s1 = ss[threadIdx.x];
            float m2 = sm[threadIdx.x + off], s2 = ss[threadIdx.x + off];
            float mm = fmaxf(m1, m2);
            sm[threadIdx.x] = mm;
            ss[threadIdx.x] = s1 * fexp(m1 - mm) + s2 * fexp(m2 - mm);
        }
        __syncthreads();
    }
    if (threadIdx.x == 0) { d_rmax[row] = sm[0]; d_rinv[row] = 1.f / ss[0]; }
}

// ---------------------------------------------------------------------------
extern "C" void kernel_launch(void* const* d_in, const int* in_sizes, int n_in,
                              void* d_out, int out_size) {
    const float* x       = (const float*)d_in[0];
    const float* pos     = (const float*)d_in[1];
    const float* w_theta = (const float*)d_in[2];
    const float* b_theta = (const float*)d_in[3];
    const float* gamma_t = (const float*)d_in[4];
    const float* beta_t  = (const float*)d_in[5];
    const float* w_g     = (const float*)d_in[6];
    const float* b_g     = (const float*)d_in[7];
    const float* w_out   = (const float*)d_in[8];
    const float* b_out   = (const float*)d_in[9];
    float* out = (float*)d_out;

    cudaFuncSetAttribute(gemm_mma<2,1,0,0>, cudaFuncAttributeMaxDynamicSharedMemorySize, GEMM_SMEM);
    cudaFuncSetAttribute(gemm_mma<1,1,0,0>, cudaFuncAttributeMaxDynamicSharedMemorySize, GEMM_SMEM);
    cudaFuncSetAttribute(gemm_mma<0,0,0,1>, cudaFuncAttributeMaxDynamicSharedMemorySize, GEMM_SMEM);
    cudaFuncSetAttribute(gemm_mma<3,1,1,0>, cudaFuncAttributeMaxDynamicSharedMemorySize, GEMM_SMEM);
    cudaFuncSetAttribute(gemm_mma<1,0,0,0>, cudaFuncAttributeMaxDynamicSharedMemorySize, GEMM_SMEM);

    float *p_xmixT, *p_tT, *p_g, *p_f, *p_yT, *p_rmax, *p_rinv, *p_wtR, *p_wgR, *p_woR;
    cudaGetSymbolAddress((void**)&p_xmixT, d_xmixT);
    cudaGetSymbolAddress((void**)&p_tT,    d_tT);
    cudaGetSymbolAddress((void**)&p_g,     d_g);
    cudaGetSymbolAddress((void**)&p_f,     d_f);
    cudaGetSymbolAddress((void**)&p_yT,    d_yT);
    cudaGetSymbolAddress((void**)&p_rmax,  d_rmax);
    cudaGetSymbolAddress((void**)&p_rinv,  d_rinv);
    cudaGetSymbolAddress((void**)&p_wtR,   d_wtR);
    cudaGetSymbolAddress((void**)&p_wgR,   d_wgR);
    cudaGetSymbolAddress((void**)&p_woR,   d_woR);

    const int TM = 74;  // ceil(9409/128)

    // 0) round weights to tf32 once per launch
    round_k<<<(C1N * CMIX + 255) / 256, 256>>>(w_theta, p_wtR, C1N * CMIX);
    round_k<<<(C2N * CMIX + 255) / 256, 256>>>(w_g,     p_wgR, C2N * CMIX);
    round_k<<<(CIN * C2N  + 255) / 256, 256>>>(w_out,   p_woR, CIN * C2N);

    // 1) xmixT = round(concat(x,pos)^T)   [9409, 1024]
    concatT_k<<<dim3(295, 16, 2), dim3(32, 8)>>>(x, pos);

    // 2) tT = round(relu(bn(xmixT @ w_theta^T)))   [9409, 256]
    gemm_mma<2,1,0,0><<<dim3(2, TM), 256, GEMM_SMEM>>>(
        p_xmixT, p_wtR, p_tT, NPIX, C1N, CMIX, CMIX, CMIX, C1N,
        b_theta, gamma_t, beta_t, 1.f, nullptr);

    // 3) g = round(w_g @ xmixT^T + b_g)   [512, LDF]
    gemm_mma<1,1,0,0><<<dim3(TM, 4), 256, GEMM_SMEM>>>(
        p_wgR, p_xmixT, p_g, C2N, NPIX, CMIX, CMIX, CMIX, LDF,
        b_g, nullptr, nullptr, 1.f, nullptr);

    // 4) f = (tT @ tT^T) / 16  — symmetric: upper-triangle tiles + mirror
    gemm_mma<0,0,0,1><<<dim3(TM, TM), 256, GEMM_SMEM>>>(
        p_tT, p_tT, p_f, NPIX, NPIX, C1N, C1N, C1N, LDF,
        nullptr, nullptr, nullptr, 0.0625f, nullptr);

    // 5) row stats: rmax, rinv = 1/sum(exp(f - rmax))
    rowstats_k<<<NPIX, 256>>>();

    // 6) yT[n,c] = rinv[n] * sum_m exp(f[n,m]-rmax[n]) g[c,m]   [9409, 512]
    //    exp fused into A-tile loader; K = LDF (pads: B cols zero)
    gemm_mma<3,1,1,0><<<dim3(4, TM), 256, GEMM_SMEM>>>(
        p_f, p_g, p_yT, NPIX, C2N, LDF, LDF, LDF, C2N,
        p_rinv, nullptr, nullptr, 1.f, p_rmax);

    // 7) out = w_out @ yT^T + b_out       [512, 9409]
    gemm_mma<1,0,0,0><<<dim3(TM, 4), 256, GEMM_SMEM>>>(
        p_woR, p_yT, out, CIN, NPIX, C2N, C2N, C2N, NPIX,
        b_out, nullptr, nullptr, 1.f, nullptr);
}

// round 7
// speedup vs baseline: 1.0006x; 1.0006x over previous
#include <cuda_runtime.h>
#include <cstdint>
#include <math.h>

#define NPIX 9409
#define LDF  9412          /* padded row stride for f/g; pads stay 0 forever */
#define CIN  512
#define CMIX 1024
#define C1N  256
#define C2N  512
#define BN_INV 0.9999950000374997f

// ------------------------- scratch (static device) --------------------------
__device__ float d_xmixT[NPIX * CMIX];        // [9409, 1024] (tf32-rounded)
__device__ float d_tT  [NPIX * C1N];          // [9409, 256]  (tf32-rounded)
__device__ float d_g   [C2N * LDF];           // [512, 9412]  (tf32-rounded)
__device__ float d_f   [NPIX * LDF];          // [9409, 9412] raw f scores
__device__ float d_yT  [NPIX * C2N];          // [9409, 512]  (tf32-rounded)
__device__ float d_rmax[NPIX];
__device__ float d_rinv[NPIX];
__device__ float d_wtR [C1N * CMIX];          // rounded weights
__device__ float d_wgR [C2N * CMIX];
__device__ float d_woR [CIN * C2N];

// ------------------------- helpers ------------------------------------------
__device__ __forceinline__ uint32_t f2tf(float v) {
    uint32_t u;
    asm("cvt.rna.tf32.f32 %0, %1;" : "=r"(u) : "f"(v));
    return u;
}
__device__ __forceinline__ float rtf(float v) { return __uint_as_float(f2tf(v)); }

__device__ __forceinline__ void mma_tf32(float c[4], uint32_t a0, uint32_t a1,
                                         uint32_t a2, uint32_t a3,
                                         uint32_t b0, uint32_t b1) {
    asm volatile(
        "mma.sync.aligned.m16n8k8.row.col.f32.tf32.tf32.f32 "
        "{%0,%1,%2,%3}, {%4,%5,%6,%7}, {%8,%9}, {%0,%1,%2,%3};"
        : "+f"(c[0]), "+f"(c[1]), "+f"(c[2]), "+f"(c[3])
        : "r"(a0), "r"(a1), "r"(a2), "r"(a3), "r"(b0), "r"(b1));
}

// fast exp on the FMA pipe (no MUFU)
__device__ __forceinline__ float fexp(float x) {
    x = fmaxf(x, -87.0f);
    float t = x * 1.4426950408889634f;
    float fl = floorf(t);
    float f = t - fl;
    float p = 1.52527338e-5f;
    p = fmaf(p, f, 1.54035304e-4f);
    p = fmaf(p, f, 1.33335581e-3f);
    p = fmaf(p, f, 9.61812911e-3f);
    p = fmaf(p, f, 5.55041087e-2f);
    p = fmaf(p, f, 2.40226507e-1f);
    p = fmaf(p, f, 6.93147181e-1f);
    p = fmaf(p, f, 1.0f);
    int i = (int)fl;
    return p * __int_as_float((i + 127) << 23);
}

// ------------------------- small prep kernels -------------------------------
__global__ void round_k(const float* __restrict__ in, float* __restrict__ out, int n) {
    int i = blockIdx.x * 256 + threadIdx.x;
    if (i < n) out[i] = rtf(in[i]);
}

// xmixT[n, k] = tf32round( (k<512) ? x[k, n] : pos[k-512, n] )
__global__ void concatT_k(const float* __restrict__ x, const float* __restrict__ pos) {
    __shared__ float tile[32][33];
    const float* S = blockIdx.z ? pos : x;
    int c0 = blockIdx.y * 32, n0 = blockIdx.x * 32;
    int tx = threadIdx.x, ty = threadIdx.y;
    #pragma unroll
    for (int i = 0; i < 32; i += 8) {
        int c = c0 + ty + i, n = n0 + tx;
        if (n < NPIX) tile[ty + i][tx] = S[(size_t)c * NPIX + n];
    }
    __syncthreads();
    int kbase = blockIdx.z * 512 + c0;
    #pragma unroll
    for (int i = 0; i < 32; i += 8) {
        int n = n0 + ty + i;
        if (n < NPIX) d_xmixT[(size_t)n * CMIX + kbase + tx] = rtf(tile[tx][ty + i]);
    }
}

// ------------------------- mma.sync tf32 GEMM, cp.async pipelined -----------
// D[M,N] = epi( sum_k A'[m,k]*B[n,k] );  A [M,K] lda, B [N,K] ldb, C [M,N] ldc
// EXPA: A'[m,k] = exp(A[m,k] - rmax[m]) (tf32-rounded); else A' = A
// EPI 0: *alpha   1: +p1[gm]   2: relu((acc+p1[gn])*p2[gn]*BN_INV+p3[gn])   3: *p1[gm]
// SYM: M==Nn, A==B; only bx>=by tiles launched; mirror-write transpose tile
#define GEMM_SMEM 73728   /* 2 buffers x (A 18432 + B 18432); >= 66048 staging */

template <int EPI, int ROUND, int EXPA, int SYM>
__global__ void __launch_bounds__(256, 2)
gemm_mma(const float* __restrict__ A, const float* __restrict__ B, float* __restrict__ C,
         int M, int Nn, int K, int lda, int ldb, int ldc,
         const float* __restrict__ p1, const float* __restrict__ p2,
         const float* __restrict__ p3, float alpha,
         const float* __restrict__ rmax) {
    if (SYM && blockIdx.y > blockIdx.x) return;
    extern __shared__ char dsm[];
    float* smf = (float*)dsm;
    const uint32_t sbase = (uint32_t)__cvta_generic_to_shared(dsm);

    const int tid  = threadIdx.x;
    const int lane = tid & 31, wid = tid >> 5;
    const int wm = wid & 1;          // 2 warp rows (64 m each)
    const int wn = wid >> 1;         // 4 warp cols (32 n each)
    const int g   = lane >> 2;       // 0..7
    const int tig = lane & 3;        // 0..3
    const int m0 = blockIdx.y * 128, n0 = blockIdx.x * 128;

    const int lr  = tid >> 3;        // 0..31
    const int kv4 = (tid & 7) << 2;  // 0,4,...,28

    float acc[4][4][4];
    #pragma unroll
    for (int mt = 0; mt < 4; ++mt)
        #pragma unroll
        for (int nt = 0; nt < 4; ++nt)
            #pragma unroll
            for (int c = 0; c < 4; ++c) acc[mt][nt][c] = 0.f;

    const int KT = (K + 31) >> 5;

    // per-thread row constants for EXPA
    float rm4[4];
    if (EXPA) {
        #pragma unroll
        for (int i = 0; i < 4; ++i) {
            int gm = m0 + lr + (i << 5);
            rm4[i] = (gm < M) ? rmax[gm] : 0.f;
        }
    }

    auto issueB = [&](int t) {
        const int gk = (t << 5) + kv4;
        uint32_t sb = sbase + (uint32_t)(t & 1) * 36864u + 18432u;
        #pragma unroll
        for (int i = 0; i < 4; ++i) {
            int row = lr + (i << 5);
            uint32_t off = (uint32_t)(row * 144 + (kv4 << 2));
            const float* pb = B + (size_t)(n0 + row) * ldb + gk;
            int szb = ((n0 + row) < Nn && gk < K) ? 16 : 0;
            if (!szb) pb = B;
            asm volatile("cp.async.cg.shared.global [%0], [%1], 16, %2;"
                         :: "r"(sb + off), "l"(pb), "r"(szb) : "memory");
        }
    };
    auto issueA_async = [&](int t) {
        const int gk = (t << 5) + kv4;
        uint32_t sa = sbase + (uint32_t)(t & 1) * 36864u;
        #pragma unroll
        for (int i = 0; i < 4; ++i) {
            int row = lr + (i << 5);
            uint32_t off = (uint32_t)(row * 144 + (kv4 << 2));
            const float* pa = A + (size_t)(m0 + row) * lda + gk;
            int sza = ((m0 + row) < M && gk < K) ? 16 : 0;
            if (!sza) pa = A;
            asm volatile("cp.async.cg.shared.global [%0], [%1], 16, %2;"
                         :: "r"(sa + off), "l"(pa), "r"(sza) : "memory");
        }
    };
    auto ldgA = [&](int t, float4 ra[4]) {
        const int gk = (t << 5) + kv4;
        #pragma unroll
        for (int i = 0; i < 4; ++i) {
            int gm = m0 + lr + (i << 5);
            ra[i] = make_float4(0.f, 0.f, 0.f, 0.f);
            if (gm < M && gk < K) ra[i] = *(const float4*)(A + (size_t)gm * lda + gk);
        }
    };
    auto stsA_exp = [&](int t, const float4 ra[4]) {
        uint32_t sa = sbase + (uint32_t)(t & 1) * 36864u;
        #pragma unroll
        for (int i = 0; i < 4; ++i) {
            int row = lr + (i << 5);
            uint32_t off = (uint32_t)(row * 144 + (kv4 << 2));
            float ex = rtf(fexp(ra[i].x - rm4[i]));
            float ey = rtf(fexp(ra[i].y - rm4[i]));
            float ez = rtf(fexp(ra[i].z - rm4[i]));
            float ew = rtf(fexp(ra[i].w - rm4[i]));
            asm volatile("st.shared.v4.b32 [%0], {%1, %2, %3, %4};"
                         :: "r"(sa + off), "r"(__float_as_uint(ex)), "r"(__float_as_uint(ey)),
                            "r"(__float_as_uint(ez)), "r"(__float_as_uint(ew)) : "memory");
        }
    };

    float4 ra[4];
    if (EXPA) {
        ldgA(0, ra);
        issueB(0);
        asm volatile("cp.async.commit_group;" ::: "memory");
    } else {
        issueA_async(0);
        issueB(0);
        asm volatile("cp.async.commit_group;" ::: "memory");
    }

    for (int t = 0; t < KT; ++t) {
        if (t + 1 < KT) {
            if (EXPA) {
                issueB(t + 1);
                asm volatile("cp.async.commit_group;" ::: "memory");
            } else {
                issueA_async(t + 1);
                issueB(t + 1);
                asm volatile("cp.async.commit_group;" ::: "memory");
            }
        }
        if (EXPA) {
            stsA_exp(t, ra);
            if (t + 1 < KT) ldgA(t + 1, ra);
        }
        if (t + 1 < KT) asm volatile("cp.async.wait_group 1;" ::: "memory");
        else            asm volatile("cp.async.wait_group 0;" ::: "memory");
        __syncthreads();

        const float* As = smf + (t & 1) * 9216;
        const float* Bs = As + 4608;

        #pragma unroll
        for (int ks = 0; ks < 4; ++ks) {
            const int kk = ks * 8;
            uint32_t bf[4][2];
            #pragma unroll
            for (int nt = 0; nt < 4; ++nt) {
                int col = wn * 32 + nt * 8 + g;
                bf[nt][0] = __float_as_uint(Bs[col * 36 + kk + tig]);
                bf[nt][1] = __float_as_uint(Bs[col * 36 + kk + tig + 4]);
            }
            #pragma unroll
            for (int mt = 0; mt < 4; ++mt) {
                int row = wm * 64 + mt * 16;
                uint32_t a0 = __float_as_uint(As[(row + g    ) * 36 + kk + tig]);
                uint32_t a1 = __float_as_uint(As[(row + g + 8) * 36 + kk + tig]);
                uint32_t a2 = __float_as_uint(As[(row + g    ) * 36 + kk + tig + 4]);
                uint32_t a3 = __float_as_uint(As[(row + g + 8) * 36 + kk + tig + 4]);
                #pragma unroll
                for (int nt = 0; nt < 4; ++nt)
                    mma_tf32(acc[mt][nt], a0, a1, a2, a3, bf[nt][0], bf[nt][1]);
            }
        }
        __syncthreads();
    }

    // ------------------------- epilogue -------------------------
    float* stg = smf;   // SYM: 128x129 staging (66 KB) — mainloop buffers dead now
    #pragma unroll
    for (int mt = 0; mt < 4; ++mt) {
        #pragma unroll
        for (int half = 0; half < 2; ++half) {
            int lm = wm * 64 + mt * 16 + g + half * 8;
            int gm = m0 + lm;
            if (gm >= M) continue;
            float rp = 0.f;
            if (EPI == 1 || EPI == 3) rp = p1[gm];
            float* crow = C + (size_t)gm * ldc;
            #pragma unroll
            for (int nt = 0; nt < 4; ++nt) {
                #pragma unroll
                for (int cc = 0; cc < 2; ++cc) {
                    int ln = wn * 32 + nt * 8 + tig * 2 + cc;
                    int gn = n0 + ln;
                    if (gn < Nn) {
                        float v = acc[mt][nt][half * 2 + cc];
                        if (EPI == 0)      v *= alpha;
                        else if (EPI == 1) v += rp;
                        else if (EPI == 2) v = fmaxf(fmaf(v + p1[gn], p2[gn] * BN_INV, p3[gn]), 0.f);
                        else               v *= rp;
                        if (ROUND) v = rtf(v);
                        crow[gn] = v;
                        if (SYM) stg[ln * 129 + lm] = v;
                    }
                }
            }
        }
    }
    if (SYM && blockIdx.x != blockIdx.y) {
        __syncthreads();
        for (int e = tid; e < 128 * 128; e += 256) {
            int ln = e >> 7, lm = e & 127;
            int gn = n0 + ln, gm = m0 + lm;
            if (gn < Nn && gm < M)
                C[(size_t)gn * ldc + gm] = stg[ln * 129 + lm];
        }
    }
}

// ------------------------- row stats: online max + sumexp -------------------
__global__ void __launch_bounds__(256) rowstats_k() {
    const int row = blockIdx.x;
    const float* p = d_f + (size_t)row * LDF;
    float m = -1e30f, s = 0.f;
    for (int q = threadIdx.x; q < 2352; q += 256) {       // quads cover 0..9407
        float4 v = *(const float4*)(p + (q << 2));
        float lm = fmaxf(fmaxf(v.x, v.y), fmaxf(v.z, v.w));
        if (lm > m) { s *= fexp(m - lm); m = lm; }
        s += fexp(v.x - m) + fexp(v.y - m) + fexp(v.z - m) + fexp(v.w - m);
    }
    if (threadIdx.x == 0) {                                // tail element 9408
        float v = p[9408];
        if (v > m) { s *= fexp(m - v); m = v; }
        s += fexp(v - m);
    }
    __shared__ float sm[256], ss[256];
    sm[threadIdx.x] = m; ss[threadIdx.x] = s;
    __syncthreads();
    for (int off = 128; off > 0; off >>= 1) {
        if (threadIdx.x < off) {
            float m1 = sm[threadIdx.x], s1 = ss[threadIdx.x];
            float m2 = sm[threadIdx.x + off], s2 = ss[threadIdx.x + off];
            float mm = fmaxf(m1, m2);
            sm[threadIdx.x] = mm;
            ss[threadIdx.x] = s1 * fexp(m1 - mm) + s2 * fexp(m2 - mm);
        }
        __syncthreads();
    }
    if (threadIdx.x == 0) { d_rmax[row] = sm[0]; d_rinv[row] = 1.f / ss[0]; }
}

// ---------------------------------------------------------------------------
extern "C" void kernel_launch(void* const* d_in, const int* in_sizes, int n_in,
                              void* d_out, int out_size) {
    const float* x       = (const float*)d_in[0];
    const float* pos     = (const float*)d_in[1];
    const float* w_theta = (const float*)d_in[2];
    const float* b_theta = (const float*)d_in[3];
    const float* gamma_t = (const float*)d_in[4];
    const float* beta_t  = (const float*)d_in[5];
    const float* w_g     = (const float*)d_in[6];
    const float* b_g     = (const float*)d_in[7];
    const float* w_out   = (const float*)d_in[8];
    const float* b_out   = (const float*)d_in[9];
    float* out = (float*)d_out;

    cudaFuncSetAttribute(gemm_mma<2,1,0,0>, cudaFuncAttributeMaxDynamicSharedMemorySize, GEMM_SMEM);
    cudaFuncSetAttribute(gemm_mma<1,1,0,0>, cudaFuncAttributeMaxDynamicSharedMemorySize, GEMM_SMEM);
    cudaFuncSetAttribute(gemm_mma<0,0,0,1>, cudaFuncAttributeMaxDynamicSharedMemorySize, GEMM_SMEM);
    cudaFuncSetAttribute(gemm_mma<3,1,1,0>, cudaFuncAttributeMaxDynamicSharedMemorySize, GEMM_SMEM);
    cudaFuncSetAttribute(gemm_mma<1,0,0,0>, cudaFuncAttributeMaxDynamicSharedMemorySize, GEMM_SMEM);

    float *p_xmixT, *p_tT, *p_g, *p_f, *p_yT, *p_rmax, *p_rinv, *p_wtR, *p_wgR, *p_woR;
    cudaGetSymbolAddress((void**)&p_xmixT, d_xmixT);
    cudaGetSymbolAddress((void**)&p_tT,    d_tT);
    cudaGetSymbolAddress((void**)&p_g,     d_g);
    cudaGetSymbolAddress((void**)&p_f,     d_f);
    cudaGetSymbolAddress((void**)&p_yT,    d_yT);
    cudaGetSymbolAddress((void**)&p_rmax,  d_rmax);
    cudaGetSymbolAddress((void**)&p_rinv,  d_rinv);
    cudaGetSymbolAddress((void**)&p_wtR,   d_wtR);
    cudaGetSymbolAddress((void**)&p_wgR,   d_wgR);
    cudaGetSymbolAddress((void**)&p_woR,   d_woR);

    const int TM = 74;  // ceil(9409/128)

    // 0) round weights to tf32 once per launch
    round_k<<<(C1N * CMIX + 255) / 256, 256>>>(w_theta, p_wtR, C1N * CMIX);
    round_k<<<(C2N * CMIX + 255) / 256, 256>>>(w_g,     p_wgR, C2N * CMIX);
    round_k<<<(CIN * C2N  + 255) / 256, 256>>>(w_out,   p_woR, CIN * C2N);

    // 1) xmixT = round(concat(x,pos)^T)   [9409, 1024]
    concatT_k<<<dim3(295, 16, 2), dim3(32, 8)>>>(x, pos);

    // 2) tT = round(relu(bn(xmixT @ w_theta^T)))   [9409, 256]
    gemm_mma<2,1,0,0><<<dim3(2, TM), 256, GEMM_SMEM>>>(
        p_xmixT, p_wtR, p_tT, NPIX, C1N, CMIX, CMIX, CMIX, C1N,
        b_theta, gamma_t, beta_t, 1.f, nullptr);

    // 3) g = round(w_g @ xmixT^T + b_g)   [512, LDF]
    gemm_mma<1,1,0,0><<<dim3(TM, 4), 256, GEMM_SMEM>>>(
        p_wgR, p_xmixT, p_g, C2N, NPIX, CMIX, CMIX, CMIX, LDF,
        b_g, nullptr, nullptr, 1.f, nullptr);

    // 4) f = (tT @ tT^T) / 16  — symmetric: upper-triangle tiles + mirror
    gemm_mma<0,0,0,1><<<dim3(TM, TM), 256, GEMM_SMEM>>>(
        p_tT, p_tT, p_f, NPIX, NPIX, C1N, C1N, C1N, LDF,
        nullptr, nullptr, nullptr, 0.0625f, nullptr);

    // 5) row stats: rmax, rinv = 1/sum(exp(f - rmax))
    rowstats_k<<<NPIX, 256>>>();

    // 6) yT[n,c] = rinv[n] * sum_m exp(f[n,m]-rmax[n]) g[c,m]   [9409, 512]
    //    exp fused into A-tile loader; K = LDF (pads: B cols zero)
    gemm_mma<3,1,1,0><<<dim3(4, TM), 256, GEMM_SMEM>>>(
        p_f, p_g, p_yT, NPIX, C2N, LDF, LDF, LDF, C2N,
        p_rinv, nullptr, nullptr, 1.f, p_rmax);

    // 7) out = w_out @ yT^T + b_out       [512, 9409]
    gemm_mma<1,0,0,0><<<dim3(TM, 4), 256, GEMM_SMEM>>>(
        p_woR, p_yT, out, CIN, NPIX, C2N, C2N, C2N, NPIX,
        b_out, nullptr, nullptr, 1.f, nullptr);
}

// round 8
// speedup vs baseline: 1.0884x; 1.0877x over previous
#include <cuda_runtime.h>
#include <cstdint>
#include <math.h>

#define NPIX 9409
#define LDF  9412          /* padded row stride for E/g; pads stay 0 forever */
#define CIN  512
#define CMIX 1024
#define C1N  256
#define C2N  512
#define BN_INV 0.9999950000374997f

// ------------------------- scratch (static device) --------------------------
__device__ float d_xmixT[NPIX * CMIX];        // [9409, 1024] (tf32-rounded)
__device__ float d_tT  [NPIX * C1N];          // [9409, 256]  (tf32-rounded)
__device__ float d_g   [C2N * LDF];           // [512, 9412]  (tf32-rounded)
__device__ float d_f   [NPIX * LDF];          // [9409, 9412] E = exp(f/16 - mhat[n])
__device__ float d_yT  [NPIX * C2N];          // [9409, 512]
__device__ float d_ds  [NPIX];                // |t_n|^2 / 16
__device__ float d_mhat[NPIX];                // sqrt(ds[n]*dsmax)
__device__ float d_denom[NPIX];               // sum_m E[n,m]
__device__ float d_dsmax;
__device__ float d_wtR [C1N * CMIX];          // rounded weights
__device__ float d_wgR [C2N * CMIX];
__device__ float d_woR [CIN * C2N];

// ------------------------- helpers ------------------------------------------
__device__ __forceinline__ uint32_t f2tf(float v) {
    uint32_t u;
    asm("cvt.rna.tf32.f32 %0, %1;" : "=r"(u) : "f"(v));
    return u;
}
__device__ __forceinline__ float rtf(float v) { return __uint_as_float(f2tf(v)); }

__device__ __forceinline__ void mma_tf32(float c[4], uint32_t a0, uint32_t a1,
                                         uint32_t a2, uint32_t a3,
                                         uint32_t b0, uint32_t b1) {
    asm volatile(
        "mma.sync.aligned.m16n8k8.row.col.f32.tf32.tf32.f32 "
        "{%0,%1,%2,%3}, {%4,%5,%6,%7}, {%8,%9}, {%0,%1,%2,%3};"
        : "+f"(c[0]), "+f"(c[1]), "+f"(c[2]), "+f"(c[3])
        : "r"(a0), "r"(a1), "r"(a2), "r"(a3), "r"(b0), "r"(b1));
}

// fast exp on the FMA pipe (no MUFU); clamp guarantees nonzero result
__device__ __forceinline__ float fexp(float x) {
    x = fmaxf(x, -87.0f);
    float t = x * 1.4426950408889634f;
    float fl = floorf(t);
    float f = t - fl;
    float p = 1.52527338e-5f;
    p = fmaf(p, f, 1.54035304e-4f);
    p = fmaf(p, f, 1.33335581e-3f);
    p = fmaf(p, f, 9.61812911e-3f);
    p = fmaf(p, f, 5.55041087e-2f);
    p = fmaf(p, f, 2.40226507e-1f);
    p = fmaf(p, f, 6.93147181e-1f);
    p = fmaf(p, f, 1.0f);
    int i = (int)fl;
    return p * __int_as_float((i + 127) << 23);
}

// ------------------------- small prep kernels -------------------------------
__global__ void zero_k() {
    int i = blockIdx.x * 256 + threadIdx.x;
    if (i < NPIX) d_denom[i] = 0.f;
    if (i == 0) d_dsmax = 0.f;
}

__global__ void round_k(const float* __restrict__ in, float* __restrict__ out, int n) {
    int i = blockIdx.x * 256 + threadIdx.x;
    if (i < n) out[i] = rtf(in[i]);
}

// xmixT[n, k] = tf32round( (k<512) ? x[k, n] : pos[k-512, n] )
__global__ void concatT_k(const float* __restrict__ x, const float* __restrict__ pos) {
    __shared__ float tile[32][33];
    const float* S = blockIdx.z ? pos : x;
    int c0 = blockIdx.y * 32, n0 = blockIdx.x * 32;
    int tx = threadIdx.x, ty = threadIdx.y;
    #pragma unroll
    for (int i = 0; i < 32; i += 8) {
        int c = c0 + ty + i, n = n0 + tx;
        if (n < NPIX) tile[ty + i][tx] = S[(size_t)c * NPIX + n];
    }
    __syncthreads();
    int kbase = blockIdx.z * 512 + c0;
    #pragma unroll
    for (int i = 0; i < 32; i += 8) {
        int n = n0 + ty + i;
        if (n < NPIX) d_xmixT[(size_t)n * CMIX + kbase + tx] = rtf(tile[tx][ty + i]);
    }
}

// ds[n] = |t_n|^2/16; dsmax = max_n ds[n] (atomicMax on nonneg floats as ints)
__global__ void __launch_bounds__(256) ds_k() {
    int row = blockIdx.x * 8 + (threadIdx.x >> 5);
    if (row >= NPIX) return;
    int lane = threadIdx.x & 31;
    const float* p = d_tT + (size_t)row * C1N;
    float s = 0.f;
    #pragma unroll
    for (int i = 0; i < 2; ++i) {
        float4 v = *(const float4*)(p + lane * 8 + i * 4);
        s += v.x * v.x + v.y * v.y + v.z * v.z + v.w * v.w;
    }
    #pragma unroll
    for (int off = 16; off > 0; off >>= 1) s += __shfl_xor_sync(0xFFFFFFFFu, s, off);
    if (lane == 0) {
        float dsv = s * 0.0625f;
        d_ds[row] = dsv;
        atomicMax((int*)&d_dsmax, __float_as_int(dsv));
    }
}

__global__ void mhat_k() {
    int i = blockIdx.x * 256 + threadIdx.x;
    if (i < NPIX) d_mhat[i] = sqrtf(d_ds[i] * d_dsmax);
}

// yT[n,c] := tf32round(yT[n,c] / denom[n])
__global__ void __launch_bounds__(256) scale_yT_k() {
    int idx = blockIdx.x * 256 + threadIdx.x;     // float4 groups
    if (idx >= NPIX * 128) return;
    int n = idx >> 7;
    float r = 1.f / d_denom[n];
    float4* p = (float4*)d_yT + idx;
    float4 v = *p;
    v.x = rtf(v.x * r); v.y = rtf(v.y * r); v.z = rtf(v.z * r); v.w = rtf(v.w * r);
    *p = v;
}

// ------------------------- mma.sync tf32 GEMM (256 thr), cp.async -----------
// D[M,N] = epi( sum_k A[m,k]*B[n,k] );  A [M,K] lda, B [N,K] ldb, C [M,N] ldc
// EPI 0: *alpha   1: +p1[gm]   2: relu((acc+p1[gn])*p2[gn]*BN_INV+p3[gn])
// EXPOUT: symmetric Gram tile kernel; writes E=exp(v*?-mhat[row]) for both
//         orientations (only bx>=by tiles launched; alpha pre-applied to v)
#define GEMM_SMEM 73728   /* 2 x (A 18432 + B 18432); >= 66048 staging */

template <int EPI, int ROUND, int EXPOUT>
__global__ void __launch_bounds__(256, 2)
gemm_mma(const float* __restrict__ A, const float* __restrict__ B, float* __restrict__ C,
         int M, int Nn, int K, int lda, int ldb, int ldc,
         const float* __restrict__ p1, const float* __restrict__ p2,
         const float* __restrict__ p3, float alpha,
         const float* __restrict__ mhat) {
    if (EXPOUT && blockIdx.y > blockIdx.x) return;
    extern __shared__ char dsm[];
    float* smf = (float*)dsm;
    const uint32_t sbase = (uint32_t)__cvta_generic_to_shared(dsm);

    const int tid  = threadIdx.x;
    const int lane = tid & 31, wid = tid >> 5;
    const int wm = wid & 1;          // 2 warp rows (64 m each)
    const int wn = wid >> 1;         // 4 warp cols (32 n each)
    const int g   = lane >> 2;       // 0..7
    const int tig = lane & 3;        // 0..3
    const int m0 = blockIdx.y * 128, n0 = blockIdx.x * 128;

    const int lr  = tid >> 3;        // 0..31
    const int kv4 = (tid & 7) << 2;  // 0,4,...,28

    float acc[4][4][4];
    #pragma unroll
    for (int mt = 0; mt < 4; ++mt)
        #pragma unroll
        for (int nt = 0; nt < 4; ++nt)
            #pragma unroll
            for (int c = 0; c < 4; ++c) acc[mt][nt][c] = 0.f;

    const int KT = (K + 31) >> 5;

    auto issue = [&](int t) {
        const int gk = (t << 5) + kv4;
        uint32_t sa = sbase + (uint32_t)(t & 1) * 36864u;
        uint32_t sb = sa + 18432u;
        #pragma unroll
        for (int i = 0; i < 4; ++i) {
            int row = lr + (i << 5);
            uint32_t off = (uint32_t)(row * 144 + (kv4 << 2));
            const float* pa = A + (size_t)(m0 + row) * lda + gk;
            int sza = ((m0 + row) < M && gk < K) ? 16 : 0;
            if (!sza) pa = A;
            asm volatile("cp.async.cg.shared.global [%0], [%1], 16, %2;"
                         :: "r"(sa + off), "l"(pa), "r"(sza) : "memory");
            const float* pb = B + (size_t)(n0 + row) * ldb + gk;
            int szb = ((n0 + row) < Nn && gk < K) ? 16 : 0;
            if (!szb) pb = B;
            asm volatile("cp.async.cg.shared.global [%0], [%1], 16, %2;"
                         :: "r"(sb + off), "l"(pb), "r"(szb) : "memory");
        }
        asm volatile("cp.async.commit_group;" ::: "memory");
    };

    issue(0);
    for (int t = 0; t < KT; ++t) {
        if (t + 1 < KT) {
            issue(t + 1);
            asm volatile("cp.async.wait_group 1;" ::: "memory");
        } else {
            asm volatile("cp.async.wait_group 0;" ::: "memory");
        }
        __syncthreads();

        const float* As = smf + (t & 1) * 9216;
        const float* Bs = As + 4608;

        #pragma unroll
        for (int ks = 0; ks < 4; ++ks) {
            const int kk = ks * 8;
            uint32_t bf[4][2];
            #pragma unroll
            for (int nt = 0; nt < 4; ++nt) {
                int col = wn * 32 + nt * 8 + g;
                bf[nt][0] = __float_as_uint(Bs[col * 36 + kk + tig]);
                bf[nt][1] = __float_as_uint(Bs[col * 36 + kk + tig + 4]);
            }
            #pragma unroll
            for (int mt = 0; mt < 4; ++mt) {
                int row = wm * 64 + mt * 16;
                uint32_t a0 = __float_as_uint(As[(row + g    ) * 36 + kk + tig]);
                uint32_t a1 = __float_as_uint(As[(row + g + 8) * 36 + kk + tig]);
                uint32_t a2 = __float_as_uint(As[(row + g    ) * 36 + kk + tig + 4]);
                uint32_t a3 = __float_as_uint(As[(row + g + 8) * 36 + kk + tig + 4]);
                #pragma unroll
                for (int nt = 0; nt < 4; ++nt)
                    mma_tf32(acc[mt][nt], a0, a1, a2, a3, bf[nt][0], bf[nt][1]);
            }
        }
        __syncthreads();
    }

    // ------------------------- epilogue -------------------------
    if (!EXPOUT) {
        #pragma unroll
        for (int mt = 0; mt < 4; ++mt) {
            #pragma unroll
            for (int half = 0; half < 2; ++half) {
                int gm = m0 + wm * 64 + mt * 16 + g + half * 8;
                if (gm >= M) continue;
                float rp = (EPI == 1) ? p1[gm] : 0.f;
                float* crow = C + (size_t)gm * ldc;
                #pragma unroll
                for (int nt = 0; nt < 4; ++nt) {
                    #pragma unroll
                    for (int cc = 0; cc < 2; ++cc) {
                        int gn = n0 + wn * 32 + nt * 8 + tig * 2 + cc;
                        if (gn < Nn) {
                            float v = acc[mt][nt][half * 2 + cc];
                            if (EPI == 0)      v *= alpha;
                            else if (EPI == 1) v += rp;
                            else               v = fmaxf(fmaf(v + p1[gn], p2[gn] * BN_INV, p3[gn]), 0.f);
                            if (ROUND) v = rtf(v);
                            crow[gn] = v;
                        }
                    }
                }
            }
        }
    } else {
        // stage raw scaled scores, then write exp for both orientations
        float* stg = smf;   // 128x129 staging (66 KB); mainloop buffers dead
        #pragma unroll
        for (int mt = 0; mt < 4; ++mt)
            #pragma unroll
            for (int half = 0; half < 2; ++half) {
                int lm = wm * 64 + mt * 16 + g + half * 8;
                #pragma unroll
                for (int nt = 0; nt < 4; ++nt)
                    #pragma unroll
                    for (int cc = 0; cc < 2; ++cc) {
                        int ln = wn * 32 + nt * 8 + tig * 2 + cc;
                        stg[lm * 129 + ln] = acc[mt][nt][half * 2 + cc] * alpha;
                    }
            }
        __syncthreads();
        const int cL = tid & 127, rO = tid >> 7;
        #pragma unroll 4
        for (int j = 0; j < 64; ++j) {
            int r = (j << 1) + rO;
            int gm = m0 + r, gn = n0 + cL;
            if (gm < M && gn < Nn)
                C[(size_t)gm * ldc + gn] = rtf(fexp(stg[r * 129 + cL] - mhat[gm]));
        }
        if (blockIdx.x != blockIdx.y) {
            #pragma unroll 4
            for (int j = 0; j < 64; ++j) {
                int r = (j << 1) + rO;
                int gn = n0 + r, gm = m0 + cL;
                if (gn < Nn && gm < M)
                    C[(size_t)gn * ldc + gm] = rtf(fexp(stg[cL * 129 + r] - mhat[gn]));
            }
        }
    }
}

// ------------------------- y-GEMM: 128x256 tile, 512 threads ----------------
// yT[n,c] = sum_m E[n,m] g[c,m];  bx==0 CTAs also accumulate denom[n]=sum_m E
#define Y_SMEM 110592   /* 2 x (A 18432 + B 36864) */

__global__ void __launch_bounds__(512, 1)
gemm_y(const float* __restrict__ A, const float* __restrict__ B,
       float* __restrict__ C, float* __restrict__ denom) {
    extern __shared__ char dsm[];
    float* smf = (float*)dsm;
    const uint32_t sbase = (uint32_t)__cvta_generic_to_shared(dsm);

    const int tid  = threadIdx.x;
    const int lane = tid & 31, wid = tid >> 5;
    const int wm = wid & 1;          // 2 warp rows (64 m each)
    const int wn = wid >> 1;         // 8 warp cols (32 n each)
    const int g   = lane >> 2;
    const int tig = lane & 3;
    const int m0 = blockIdx.y * 128, n0 = blockIdx.x * 256;
    const int M = NPIX, K = LDF;
    const bool dflag = (blockIdx.x == 0);

    const int lr  = tid >> 3;        // 0..63
    const int kv4 = (tid & 7) << 2;

    float acc[4][4][4];
    #pragma unroll
    for (int mt = 0; mt < 4; ++mt)
        #pragma unroll
        for (int nt = 0; nt < 4; ++nt)
            #pragma unroll
            for (int c = 0; c < 4; ++c) acc[mt][nt][c] = 0.f;
    float part0 = 0.f, part1 = 0.f;

    auto issue = [&](int t) {
        const int gk = (t << 5) + kv4;
        uint32_t sa = sbase + (uint32_t)(t & 1) * 55296u;
        uint32_t sb = sa + 18432u;
        #pragma unroll
        for (int i = 0; i < 2; ++i) {
            int row = lr + (i << 6);
            uint32_t off = (uint32_t)(row * 144 + (kv4 << 2));
            const float* pa = A + (size_t)(m0 + row) * K + gk;
            int sza = ((m0 + row) < M && gk < K) ? 16 : 0;
            if (!sza) pa = A;
            asm volatile("cp.async.cg.shared.global [%0], [%1], 16, %2;"
                         :: "r"(sa + off), "l"(pa), "r"(sza) : "memory");
        }
        #pragma unroll
        for (int i = 0; i < 4; ++i) {
            int row = lr + (i << 6);
            uint32_t off = (uint32_t)(row * 144 + (kv4 << 2));
            const float* pb = B + (size_t)(n0 + row) * K + gk;
            int szb = (gk < K) ? 16 : 0;
            if (!szb) pb = B;
            asm volatile("cp.async.cg.shared.global [%0], [%1], 16, %2;"
                         :: "r"(sb + off), "l"(pb), "r"(szb) : "memory");
        }
        asm volatile("cp.async.commit_group;" ::: "memory");
    };

    const int KT = (K + 31) >> 5;   // 295
    issue(0);
    for (int t = 0; t < KT; ++t) {
        if (t + 1 < KT) {
            issue(t + 1);
            asm volatile("cp.async.wait_group 1;" ::: "memory");
        } else {
            asm volatile("cp.async.wait_group 0;" ::: "memory");
        }
        __syncthreads();

        const float* As = smf + (t & 1) * 13824;
        const float* Bs = As + 4608;

        if (dflag) {   // row sums of E for the softmax denominator
            float4 v0 = *(const float4*)&As[lr * 36 + kv4];
            float4 v1 = *(const float4*)&As[(lr + 64) * 36 + kv4];
            part0 += v0.x + v0.y + v0.z + v0.w;
            part1 += v1.x + v1.y + v1.z + v1.w;
        }

        #pragma unroll
        for (int ks = 0; ks < 4; ++ks) {
            const int kk = ks * 8;
            uint32_t bf[4][2];
            #pragma unroll
            for (int nt = 0; nt < 4; ++nt) {
                int col = wn * 32 + nt * 8 + g;
                bf[nt][0] = __float_as_uint(Bs[col * 36 + kk + tig]);
                bf[nt][1] = __float_as_uint(Bs[col * 36 + kk + tig + 4]);
            }
            #pragma unroll
            for (int mt = 0; mt < 4; ++mt) {
                int row = wm * 64 + mt * 16;
                uint32_t a0 = __float_as_uint(As[(row + g    ) * 36 + kk + tig]);
                uint32_t a1 = __float_as_uint(As[(row + g + 8) * 36 + kk + tig]);
                uint32_t a2 = __float_as_uint(As[(row + g    ) * 36 + kk + tig + 4]);
                uint32_t a3 = __float_as_uint(As[(row + g + 8) * 36 + kk + tig + 4]);
                #pragma unroll
                for (int nt = 0; nt < 4; ++nt)
                    mma_tf32(acc[mt][nt], a0, a1, a2, a3, bf[nt][0], bf[nt][1]);
            }
        }
        __syncthreads();
    }

    if (dflag) {
        int gm0 = m0 + lr;
        if (gm0 < M) atomicAdd(&denom[gm0], part0);
        int gm1 = m0 + lr + 64;
        if (gm1 < M) atomicAdd(&denom[gm1], part1);
    }

    #pragma unroll
    for (int mt = 0; mt < 4; ++mt) {
        #pragma unroll
        for (int half = 0; half < 2; ++half) {
            int gm = m0 + wm * 64 + mt * 16 + g + half * 8;
            if (gm >= M) continue;
            float* crow = C + (size_t)gm * C2N;
            #pragma unroll
            for (int nt = 0; nt < 4; ++nt) {
                #pragma unroll
                for (int cc = 0; cc < 2; ++cc) {
                    int gn = n0 + wn * 32 + nt * 8 + tig * 2 + cc;
                    crow[gn] = acc[mt][nt][half * 2 + cc];
                }
            }
        }
    }
}

// ---------------------------------------------------------------------------
extern "C" void kernel_launch(void* const* d_in, const int* in_sizes, int n_in,
                              void* d_out, int out_size) {
    const float* x       = (const float*)d_in[0];
    const float* pos     = (const float*)d_in[1];
    const float* w_theta = (const float*)d_in[2];
    const float* b_theta = (const float*)d_in[3];
    const float* gamma_t = (const float*)d_in[4];
    const float* beta_t  = (const float*)d_in[5];
    const float* w_g     = (const float*)d_in[6];
    const float* b_g     = (const float*)d_in[7];
    const float* w_out   = (const float*)d_in[8];
    const float* b_out   = (const float*)d_in[9];
    float* out = (float*)d_out;

    cudaFuncSetAttribute(gemm_mma<2,1,0>, cudaFuncAttributeMaxDynamicSharedMemorySize, GEMM_SMEM);
    cudaFuncSetAttribute(gemm_mma<1,1,0>, cudaFuncAttributeMaxDynamicSharedMemorySize, GEMM_SMEM);
    cudaFuncSetAttribute(gemm_mma<0,0,1>, cudaFuncAttributeMaxDynamicSharedMemorySize, GEMM_SMEM);
    cudaFuncSetAttribute(gemm_mma<1,0,0>, cudaFuncAttributeMaxDynamicSharedMemorySize, GEMM_SMEM);
    cudaFuncSetAttribute(gemm_y,          cudaFuncAttributeMaxDynamicSharedMemorySize, Y_SMEM);

    float *p_xmixT, *p_tT, *p_g, *p_f, *p_yT, *p_mhat, *p_denom, *p_wtR, *p_wgR, *p_woR;
    cudaGetSymbolAddress((void**)&p_xmixT, d_xmixT);
    cudaGetSymbolAddress((void**)&p_tT,    d_tT);
    cudaGetSymbolAddress((void**)&p_g,     d_g);
    cudaGetSymbolAddress((void**)&p_f,     d_f);
    cudaGetSymbolAddress((void**)&p_yT,    d_yT);
    cudaGetSymbolAddress((void**)&p_mhat,  d_mhat);
    cudaGetSymbolAddress((void**)&p_denom, d_denom);
    cudaGetSymbolAddress((void**)&p_wtR,   d_wtR);
    cudaGetSymbolAddress((void**)&p_wgR,   d_wgR);
    cudaGetSymbolAddress((void**)&p_woR,   d_woR);

    const int TM = 74;  // ceil(9409/128)

    // 0) reset accumulators (graph-replay safe) + round weights to tf32
    zero_k<<<37, 256>>>();
    round_k<<<(C1N * CMIX + 255) / 256, 256>>>(w_theta, p_wtR, C1N * CMIX);
    round_k<<<(C2N * CMIX + 255) / 256, 256>>>(w_g,     p_wgR, C2N * CMIX);
    round_k<<<(CIN * C2N  + 255) / 256, 256>>>(w_out,   p_woR, CIN * C2N);

    // 1) xmixT = round(concat(x,pos)^T)   [9409, 1024]
    concatT_k<<<dim3(295, 16, 2), dim3(32, 8)>>>(x, pos);

    // 2) tT = round(relu(bn(xmixT @ w_theta^T)))   [9409, 256]
    gemm_mma<2,1,0><<<dim3(2, TM), 256, GEMM_SMEM>>>(
        p_xmixT, p_wtR, p_tT, NPIX, C1N, CMIX, CMIX, CMIX, C1N,
        b_theta, gamma_t, beta_t, 1.f, nullptr);

    // 3) ds[n] = |t_n|^2/16, dsmax; mhat[n] = sqrt(ds[n]*dsmax)  (>= row max)
    ds_k<<<(NPIX + 7) / 8, 256>>>();
    mhat_k<<<37, 256>>>();

    // 4) g = round(w_g @ xmixT^T + b_g)   [512, LDF]
    gemm_mma<1,1,0><<<dim3(TM, 4), 256, GEMM_SMEM>>>(
        p_wgR, p_xmixT, p_g, C2N, NPIX, CMIX, CMIX, CMIX, LDF,
        b_g, nullptr, nullptr, 1.f, nullptr);

    // 5) E = exp(tT@tT^T/16 - mhat[row])  — symmetric tiles + mirror, exp fused
    gemm_mma<0,0,1><<<dim3(TM, TM), 256, GEMM_SMEM>>>(
        p_tT, p_tT, p_f, NPIX, NPIX, C1N, C1N, C1N, LDF,
        nullptr, nullptr, nullptr, 0.0625f, p_mhat);

    // 6) yT[n,c] = sum_m E[n,m] g[c,m]; bx==0 also accumulates denom[n]
    gemm_y<<<dim3(2, TM), 512, Y_SMEM>>>(p_f, p_g, p_yT, p_denom);

    // 7) yT *= 1/denom  (tf32-rounded)
    scale_yT_k<<<(NPIX * 128 + 255) / 256, 256>>>();

    // 8) out = w_out @ yT^T + b_out       [512, 9409]
    gemm_mma<1,0,0><<<dim3(TM, 4), 256, GEMM_SMEM>>>(
        p_woR, p_yT, out, CIN, NPIX, C2N, C2N, C2N, NPIX,
        b_out, nullptr, nullptr, 1.f, nullptr);
}

// round 9
// speedup vs baseline: 1.1428x; 1.0500x over previous
#include <cuda_runtime.h>
#include <cstdint>
#include <math.h>

#define NPIX 9409
#define LDF  9412          /* padded row stride for E/g; pads stay 0 forever */
#define CIN  512
#define CMIX 1024
#define C1N  256
#define C2N  512
#define BN_INV 0.9999950000374997f

// ------------------------- scratch (static device) --------------------------
__device__ float d_xmixT[NPIX * CMIX];        // [9409, 1024] (tf32-rounded)
__device__ float d_tT  [NPIX * C1N];          // [9409, 256]  (tf32-rounded)
__device__ float d_g   [C2N * LDF];           // [512, 9412]  (tf32-rounded)
__device__ float d_f   [NPIX * LDF];          // [9409, 9412] E = exp(f/16 - mhat[n])
__device__ float d_yT  [NPIX * C2N];          // [9409, 512]
__device__ float d_ds  [NPIX];                // |t_n|^2 / 16
__device__ float d_mhat[NPIX];                // sqrt(ds[n]*dsmax)
__device__ float d_denom[NPIX];               // sum_m E[n,m]
__device__ float d_dsmax;
__device__ float d_wtR [C1N * CMIX];          // rounded weights
__device__ float d_wgR [C2N * CMIX];
__device__ float d_woR [CIN * C2N];

// ------------------------- helpers ------------------------------------------
__device__ __forceinline__ uint32_t f2tf(float v) {
    uint32_t u;
    asm("cvt.rna.tf32.f32 %0, %1;" : "=r"(u) : "f"(v));
    return u;
}
__device__ __forceinline__ float rtf(float v) { return __uint_as_float(f2tf(v)); }

__device__ __forceinline__ void mma_tf32(float c[4], uint32_t a0, uint32_t a1,
                                         uint32_t a2, uint32_t a3,
                                         uint32_t b0, uint32_t b1) {
    asm volatile(
        "mma.sync.aligned.m16n8k8.row.col.f32.tf32.tf32.f32 "
        "{%0,%1,%2,%3}, {%4,%5,%6,%7}, {%8,%9}, {%0,%1,%2,%3};"
        : "+f"(c[0]), "+f"(c[1]), "+f"(c[2]), "+f"(c[3])
        : "r"(a0), "r"(a1), "r"(a2), "r"(a3), "r"(b0), "r"(b1));
}

// fast exp on the FMA pipe (no MUFU); clamp guarantees nonzero result
__device__ __forceinline__ float fexp(float x) {
    x = fmaxf(x, -87.0f);
    float t = x * 1.4426950408889634f;
    float fl = floorf(t);
    float f = t - fl;
    float p = 1.52527338e-5f;
    p = fmaf(p, f, 1.54035304e-4f);
    p = fmaf(p, f, 1.33335581e-3f);
    p = fmaf(p, f, 9.61812911e-3f);
    p = fmaf(p, f, 5.55041087e-2f);
    p = fmaf(p, f, 2.40226507e-1f);
    p = fmaf(p, f, 6.93147181e-1f);
    p = fmaf(p, f, 1.0f);
    int i = (int)fl;
    return p * __int_as_float((i + 127) << 23);
}

// ------------------------- small prep kernels -------------------------------
__global__ void zero_k() {
    int i = blockIdx.x * 256 + threadIdx.x;
    if (i < NPIX) d_denom[i] = 0.f;
    if (i == 0) d_dsmax = 0.f;
}

__global__ void round_k(const float* __restrict__ in, float* __restrict__ out, int n) {
    int i = blockIdx.x * 256 + threadIdx.x;
    if (i < n) out[i] = rtf(in[i]);
}

// xmixT[n, k] = tf32round( (k<512) ? x[k, n] : pos[k-512, n] )
__global__ void concatT_k(const float* __restrict__ x, const float* __restrict__ pos) {
    __shared__ float tile[32][33];
    const float* S = blockIdx.z ? pos : x;
    int c0 = blockIdx.y * 32, n0 = blockIdx.x * 32;
    int tx = threadIdx.x, ty = threadIdx.y;
    #pragma unroll
    for (int i = 0; i < 32; i += 8) {
        int c = c0 + ty + i, n = n0 + tx;
        if (n < NPIX) tile[ty + i][tx] = S[(size_t)c * NPIX + n];
    }
    __syncthreads();
    int kbase = blockIdx.z * 512 + c0;
    #pragma unroll
    for (int i = 0; i < 32; i += 8) {
        int n = n0 + ty + i;
        if (n < NPIX) d_xmixT[(size_t)n * CMIX + kbase + tx] = rtf(tile[tx][ty + i]);
    }
}

// ds[n] = |t_n|^2/16; dsmax = max_n ds[n] (atomicMax on nonneg floats as ints)
__global__ void __launch_bounds__(256) ds_k() {
    int row = blockIdx.x * 8 + (threadIdx.x >> 5);
    if (row >= NPIX) return;
    int lane = threadIdx.x & 31;
    const float* p = d_tT + (size_t)row * C1N;
    float s = 0.f;
    #pragma unroll
    for (int i = 0; i < 2; ++i) {
        float4 v = *(const float4*)(p + lane * 8 + i * 4);
        s += v.x * v.x + v.y * v.y + v.z * v.z + v.w * v.w;
    }
    #pragma unroll
    for (int off = 16; off > 0; off >>= 1) s += __shfl_xor_sync(0xFFFFFFFFu, s, off);
    if (lane == 0) {
        float dsv = s * 0.0625f;
        d_ds[row] = dsv;
        atomicMax((int*)&d_dsmax, __float_as_int(dsv));
    }
}

__global__ void mhat_k() {
    int i = blockIdx.x * 256 + threadIdx.x;
    if (i < NPIX) d_mhat[i] = sqrtf(d_ds[i] * d_dsmax);
}

// yT[n,c] := tf32round(yT[n,c] / denom[n])
__global__ void __launch_bounds__(256) scale_yT_k() {
    int idx = blockIdx.x * 256 + threadIdx.x;     // float4 groups
    if (idx >= NPIX * 128) return;
    int n = idx >> 7;
    float r = 1.f / d_denom[n];
    float4* p = (float4*)d_yT + idx;
    float4 v = *p;
    v.x = rtf(v.x * r); v.y = rtf(v.y * r); v.z = rtf(v.z * r); v.w = rtf(v.w * r);
    *p = v;
}

// ------------------------- mma.sync tf32 GEMM (256 thr), cp.async -----------
// D[M,N] = epi( sum_k A[m,k]*B[n,k] );  A [M,K] lda, B [N,K] ldb, C [M,N] ldc
// EPI 0: *alpha   1: +p1[gm]   2: relu((acc+p1[gn])*p2[gn]*BN_INV+p3[gn])
// EXPOUT: symmetric Gram tile kernel; writes E=exp(v*?-mhat[row]) for both
//         orientations (only bx>=by tiles launched; alpha pre-applied to v)
#define GEMM_SMEM 73728   /* 2 x (A 18432 + B 18432); >= 66048 staging */

template <int EPI, int ROUND, int EXPOUT>
__global__ void __launch_bounds__(256, 2)
gemm_mma(const float* __restrict__ A, const float* __restrict__ B, float* __restrict__ C,
         int M, int Nn, int K, int lda, int ldb, int ldc,
         const float* __restrict__ p1, const float* __restrict__ p2,
         const float* __restrict__ p3, float alpha,
         const float* __restrict__ mhat) {
    if (EXPOUT && blockIdx.y > blockIdx.x) return;
    extern __shared__ char dsm[];
    float* smf = (float*)dsm;
    const uint32_t sbase = (uint32_t)__cvta_generic_to_shared(dsm);

    const int tid  = threadIdx.x;
    const int lane = tid & 31, wid = tid >> 5;
    const int wm = wid & 1;          // 2 warp rows (64 m each)
    const int wn = wid >> 1;         // 4 warp cols (32 n each)
    const int g   = lane >> 2;       // 0..7
    const int tig = lane & 3;        // 0..3
    const int m0 = blockIdx.y * 128, n0 = blockIdx.x * 128;

    const int lr  = tid >> 3;        // 0..31
    const int kv4 = (tid & 7) << 2;  // 0,4,...,28

    float acc[4][4][4];
    #pragma unroll
    for (int mt = 0; mt < 4; ++mt)
        #pragma unroll
        for (int nt = 0; nt < 4; ++nt)
            #pragma unroll
            for (int c = 0; c < 4; ++c) acc[mt][nt][c] = 0.f;

    const int KT = (K + 31) >> 5;

    auto issue = [&](int t) {
        const int gk = (t << 5) + kv4;
        uint32_t sa = sbase + (uint32_t)(t & 1) * 36864u;
        uint32_t sb = sa + 18432u;
        #pragma unroll
        for (int i = 0; i < 4; ++i) {
            int row = lr + (i << 5);
            uint32_t off = (uint32_t)(row * 144 + (kv4 << 2));
            const float* pa = A + (size_t)(m0 + row) * lda + gk;
            int sza = ((m0 + row) < M && gk < K) ? 16 : 0;
            if (!sza) pa = A;
            asm volatile("cp.async.cg.shared.global [%0], [%1], 16, %2;"
                         :: "r"(sa + off), "l"(pa), "r"(sza) : "memory");
            const float* pb = B + (size_t)(n0 + row) * ldb + gk;
            int szb = ((n0 + row) < Nn && gk < K) ? 16 : 0;
            if (!szb) pb = B;
            asm volatile("cp.async.cg.shared.global [%0], [%1], 16, %2;"
                         :: "r"(sb + off), "l"(pb), "r"(szb) : "memory");
        }
        asm volatile("cp.async.commit_group;" ::: "memory");
    };

    issue(0);
    for (int t = 0; t < KT; ++t) {
        if (t + 1 < KT) {
            issue(t + 1);
            asm volatile("cp.async.wait_group 1;" ::: "memory");
        } else {
            asm volatile("cp.async.wait_group 0;" ::: "memory");
        }
        __syncthreads();

        const float* As = smf + (t & 1) * 9216;
        const float* Bs = As + 4608;

        #pragma unroll
        for (int ks = 0; ks < 4; ++ks) {
            const int kk = ks * 8;
            uint32_t bf[4][2];
            #pragma unroll
            for (int nt = 0; nt < 4; ++nt) {
                int col = wn * 32 + nt * 8 + g;
                bf[nt][0] = __float_as_uint(Bs[col * 36 + kk + tig]);
                bf[nt][1] = __float_as_uint(Bs[col * 36 + kk + tig + 4]);
            }
            #pragma unroll
            for (int mt = 0; mt < 4; ++mt) {
                int row = wm * 64 + mt * 16;
                uint32_t a0 = __float_as_uint(As[(row + g    ) * 36 + kk + tig]);
                uint32_t a1 = __float_as_uint(As[(row + g + 8) * 36 + kk + tig]);
                uint32_t a2 = __float_as_uint(As[(row + g    ) * 36 + kk + tig + 4]);
                uint32_t a3 = __float_as_uint(As[(row + g + 8) * 36 + kk + tig + 4]);
                #pragma unroll
                for (int nt = 0; nt < 4; ++nt)
                    mma_tf32(acc[mt][nt], a0, a1, a2, a3, bf[nt][0], bf[nt][1]);
            }
        }
        __syncthreads();
    }

    // ------------------------- epilogue -------------------------
    if (!EXPOUT) {
        #pragma unroll
        for (int mt = 0; mt < 4; ++mt) {
            #pragma unroll
            for (int half = 0; half < 2; ++half) {
                int gm = m0 + wm * 64 + mt * 16 + g + half * 8;
                if (gm >= M) continue;
                float rp = (EPI == 1) ? p1[gm] : 0.f;
                float* crow = C + (size_t)gm * ldc;
                #pragma unroll
                for (int nt = 0; nt < 4; ++nt) {
                    #pragma unroll
                    for (int cc = 0; cc < 2; ++cc) {
                        int gn = n0 + wn * 32 + nt * 8 + tig * 2 + cc;
                        if (gn < Nn) {
                            float v = acc[mt][nt][half * 2 + cc];
                            if (EPI == 0)      v *= alpha;
                            else if (EPI == 1) v += rp;
                            else               v = fmaxf(fmaf(v + p1[gn], p2[gn] * BN_INV, p3[gn]), 0.f);
                            if (ROUND) v = rtf(v);
                            crow[gn] = v;
                        }
                    }
                }
            }
        }
    } else {
        // stage raw scaled scores, then write exp for both orientations
        float* stg = smf;   // 128x129 staging (66 KB); mainloop buffers dead
        #pragma unroll
        for (int mt = 0; mt < 4; ++mt)
            #pragma unroll
            for (int half = 0; half < 2; ++half) {
                int lm = wm * 64 + mt * 16 + g + half * 8;
                #pragma unroll
                for (int nt = 0; nt < 4; ++nt)
                    #pragma unroll
                    for (int cc = 0; cc < 2; ++cc) {
                        int ln = wn * 32 + nt * 8 + tig * 2 + cc;
                        stg[lm * 129 + ln] = acc[mt][nt][half * 2 + cc] * alpha;
                    }
            }
        __syncthreads();
        const int cL = tid & 127, rO = tid >> 7;
        #pragma unroll 4
        for (int j = 0; j < 64; ++j) {
            int r = (j << 1) + rO;
            int gm = m0 + r, gn = n0 + cL;
            if (gm < M && gn < Nn)
                C[(size_t)gm * ldc + gn] = rtf(fexp(stg[r * 129 + cL] - mhat[gm]));
        }
        if (blockIdx.x != blockIdx.y) {
            #pragma unroll 4
            for (int j = 0; j < 64; ++j) {
                int r = (j << 1) + rO;
                int gn = n0 + r, gm = m0 + cL;
                if (gn < Nn && gm < M)
                    C[(size_t)gn * ldc + gm] = rtf(fexp(stg[cL * 129 + r] - mhat[gn]));
            }
        }
    }
}

// ------------------------- y-GEMM: 128x256 tile, 256 thr, warp 64x64 --------
// yT[n,c] = sum_m E[n,m] g[c,m]; each CTA also sums 64 of its E rows -> denom
// 3-stage cp.async pipeline, single __syncthreads per k-tile
#define Y_SMEM 165888   /* 3 stages x (A 18432 + B 36864) */

__global__ void __launch_bounds__(256, 1)
gemm_y(const float* __restrict__ A, const float* __restrict__ B,
       float* __restrict__ C, float* __restrict__ denom) {
    extern __shared__ char dsm[];
    float* smf = (float*)dsm;
    const uint32_t sbase = (uint32_t)__cvta_generic_to_shared(dsm);

    const int tid  = threadIdx.x;
    const int lane = tid & 31, wid = tid >> 5;
    const int wm = wid & 1;          // 2 warp rows (64 m each)
    const int wn = wid >> 1;         // 4 warp cols (64 n each)
    const int g   = lane >> 2;
    const int tig = lane & 3;
    const int m0 = blockIdx.y * 128, n0 = blockIdx.x * 256;
    const int M = NPIX, K = LDF;

    float acc[4][8][4];
    #pragma unroll
    for (int mt = 0; mt < 4; ++mt)
        #pragma unroll
        for (int nt = 0; nt < 8; ++nt)
            #pragma unroll
            for (int c = 0; c < 4; ++c) acc[mt][nt][c] = 0.f;
    float dpart = 0.f;
    // denom rows: this CTA sums A rows [bx*64, bx*64+64); 4 threads per row
    const int drow = (blockIdx.x << 6) + (tid >> 2);   // local row in A tile
    const int dq   = (tid & 3) * 8;                    // 8 floats per thread

    auto issue = [&](int t) {
        const int stage = t % 3;
        uint32_t sa = sbase + (uint32_t)stage * 55296u;
        uint32_t sb = sa + 18432u;
        const int kbase = t << 5;
        #pragma unroll
        for (int i = 0; i < 4; ++i) {        // A: 128 rows x 8 chunks
            int id = tid + (i << 8);
            int row = id >> 3, ch = id & 7;
            int gk = kbase + (ch << 2);
            uint32_t off = (uint32_t)(row * 144 + (ch << 4));
            const float* pa = A + (size_t)(m0 + row) * K + gk;
            int sza = ((m0 + row) < M && gk < K) ? 16 : 0;
            if (!sza) pa = A;
            asm volatile("cp.async.cg.shared.global [%0], [%1], 16, %2;"
                         :: "r"(sa + off), "l"(pa), "r"(sza) : "memory");
        }
        #pragma unroll
        for (int i = 0; i < 8; ++i) {        // B: 256 rows x 8 chunks
            int id = tid + (i << 8);
            int row = id >> 3, ch = id & 7;
            int gk = kbase + (ch << 2);
            uint32_t off = (uint32_t)(row * 144 + (ch << 4));
            const float* pb = B + (size_t)(n0 + row) * K + gk;
            int szb = (gk < K) ? 16 : 0;
            if (!szb) pb = B;
            asm volatile("cp.async.cg.shared.global [%0], [%1], 16, %2;"
                         :: "r"(sb + off), "l"(pb), "r"(szb) : "memory");
        }
        asm volatile("cp.async.commit_group;" ::: "memory");
    };

    const int KT = (K + 31) >> 5;   // 295
    issue(0);
    if (KT > 1) issue(1);
    for (int t = 0; t < KT; ++t) {
        if (t + 1 < KT) asm volatile("cp.async.wait_group 1;" ::: "memory");
        else            asm volatile("cp.async.wait_group 0;" ::: "memory");
        __syncthreads();
        if (t + 2 < KT) issue(t + 2);

        const float* As = smf + (t % 3) * 13824;
        const float* Bs = As + 4608;

        // denom partial: 8 floats of one A row
        {
            float4 v0 = *(const float4*)&As[drow * 36 + dq];
            float4 v1 = *(const float4*)&As[drow * 36 + dq + 4];
            dpart += (v0.x + v0.y) + (v0.z + v0.w) + (v1.x + v1.y) + (v1.z + v1.w);
        }

        #pragma unroll
        for (int ks = 0; ks < 4; ++ks) {
            const int kk = ks * 8;
            uint32_t bf[8][2];
            #pragma unroll
            for (int nt = 0; nt < 8; ++nt) {
                int col = wn * 64 + nt * 8 + g;
                bf[nt][0] = __float_as_uint(Bs[col * 36 + kk + tig]);
                bf[nt][1] = __float_as_uint(Bs[col * 36 + kk + tig + 4]);
            }
            #pragma unroll
            for (int mt = 0; mt < 4; ++mt) {
                int row = wm * 64 + mt * 16;
                uint32_t a0 = __float_as_uint(As[(row + g    ) * 36 + kk + tig]);
                uint32_t a1 = __float_as_uint(As[(row + g + 8) * 36 + kk + tig]);
                uint32_t a2 = __float_as_uint(As[(row + g    ) * 36 + kk + tig + 4]);
                uint32_t a3 = __float_as_uint(As[(row + g + 8) * 36 + kk + tig + 4]);
                #pragma unroll
                for (int nt = 0; nt < 8; ++nt)
                    mma_tf32(acc[mt][nt], a0, a1, a2, a3, bf[nt][0], bf[nt][1]);
            }
        }
    }

    // denom reduce: 4 consecutive lanes share a row
    dpart += __shfl_xor_sync(0xFFFFFFFFu, dpart, 1);
    dpart += __shfl_xor_sync(0xFFFFFFFFu, dpart, 2);
    if ((tid & 3) == 0) {
        int gm = m0 + drow;
        if (gm < M) atomicAdd(&denom[gm], dpart);
    }

    #pragma unroll
    for (int mt = 0; mt < 4; ++mt) {
        #pragma unroll
        for (int half = 0; half < 2; ++half) {
            int gm = m0 + wm * 64 + mt * 16 + g + half * 8;
            if (gm >= M) continue;
            float* crow = C + (size_t)gm * C2N;
            #pragma unroll
            for (int nt = 0; nt < 8; ++nt) {
                #pragma unroll
                for (int cc = 0; cc < 2; ++cc) {
                    int gn = n0 + wn * 64 + nt * 8 + tig * 2 + cc;
                    crow[gn] = acc[mt][nt][half * 2 + cc];
                }
            }
        }
    }
}

// ---------------------------------------------------------------------------
extern "C" void kernel_launch(void* const* d_in, const int* in_sizes, int n_in,
                              void* d_out, int out_size) {
    const float* x       = (const float*)d_in[0];
    const float* pos     = (const float*)d_in[1];
    const float* w_theta = (const float*)d_in[2];
    const float* b_theta = (const float*)d_in[3];
    const float* gamma_t = (const float*)d_in[4];
    const float* beta_t  = (const float*)d_in[5];
    const float* w_g     = (const float*)d_in[6];
    const float* b_g     = (const float*)d_in[7];
    const float* w_out   = (const float*)d_in[8];
    const float* b_out   = (const float*)d_in[9];
    float* out = (float*)d_out;

    cudaFuncSetAttribute(gemm_mma<2,1,0>, cudaFuncAttributeMaxDynamicSharedMemorySize, GEMM_SMEM);
    cudaFuncSetAttribute(gemm_mma<1,1,0>, cudaFuncAttributeMaxDynamicSharedMemorySize, GEMM_SMEM);
    cudaFuncSetAttribute(gemm_mma<0,0,1>, cudaFuncAttributeMaxDynamicSharedMemorySize, GEMM_SMEM);
    cudaFuncSetAttribute(gemm_mma<1,0,0>, cudaFuncAttributeMaxDynamicSharedMemorySize, GEMM_SMEM);
    cudaFuncSetAttribute(gemm_y,          cudaFuncAttributeMaxDynamicSharedMemorySize, Y_SMEM);

    float *p_xmixT, *p_tT, *p_g, *p_f, *p_yT, *p_mhat, *p_denom, *p_wtR, *p_wgR, *p_woR;
    cudaGetSymbolAddress((void**)&p_xmixT, d_xmixT);
    cudaGetSymbolAddress((void**)&p_tT,    d_tT);
    cudaGetSymbolAddress((void**)&p_g,     d_g);
    cudaGetSymbolAddress((void**)&p_f,     d_f);
    cudaGetSymbolAddress((void**)&p_yT,    d_yT);
    cudaGetSymbolAddress((void**)&p_mhat,  d_mhat);
    cudaGetSymbolAddress((void**)&p_denom, d_denom);
    cudaGetSymbolAddress((void**)&p_wtR,   d_wtR);
    cudaGetSymbolAddress((void**)&p_wgR,   d_wgR);
    cudaGetSymbolAddress((void**)&p_woR,   d_woR);

    const int TM = 74;  // ceil(9409/128)

    // 0) reset accumulators (graph-replay safe) + round weights to tf32
    zero_k<<<37, 256>>>();
    round_k<<<(C1N * CMIX + 255) / 256, 256>>>(w_theta, p_wtR, C1N * CMIX);
    round_k<<<(C2N * CMIX + 255) / 256, 256>>>(w_g,     p_wgR, C2N * CMIX);
    round_k<<<(CIN * C2N  + 255) / 256, 256>>>(w_out,   p_woR, CIN * C2N);

    // 1) xmixT = round(concat(x,pos)^T)   [9409, 1024]
    concatT_k<<<dim3(295, 16, 2), dim3(32, 8)>>>(x, pos);

    // 2) tT = round(relu(bn(xmixT @ w_theta^T)))   [9409, 256]
    gemm_mma<2,1,0><<<dim3(2, TM), 256, GEMM_SMEM>>>(
        p_xmixT, p_wtR, p_tT, NPIX, C1N, CMIX, CMIX, CMIX, C1N,
        b_theta, gamma_t, beta_t, 1.f, nullptr);

    // 3) ds[n] = |t_n|^2/16, dsmax; mhat[n] = sqrt(ds[n]*dsmax)  (>= row max)
    ds_k<<<(NPIX + 7) / 8, 256>>>();
    mhat_k<<<37, 256>>>();

    // 4) g = round(w_g @ xmixT^T + b_g)   [512, LDF]
    gemm_mma<1,1,0><<<dim3(TM, 4), 256, GEMM_SMEM>>>(
        p_wgR, p_xmixT, p_g, C2N, NPIX, CMIX, CMIX, CMIX, LDF,
        b_g, nullptr, nullptr, 1.f, nullptr);

    // 5) E = exp(tT@tT^T/16 - mhat[row])  — symmetric tiles + mirror, exp fused
    gemm_mma<0,0,1><<<dim3(TM, TM), 256, GEMM_SMEM>>>(
        p_tT, p_tT, p_f, NPIX, NPIX, C1N, C1N, C1N, LDF,
        nullptr, nullptr, nullptr, 0.0625f, p_mhat);

    // 6) yT[n,c] = sum_m E[n,m] g[c,m]; CTAs also accumulate denom[n]
    gemm_y<<<dim3(2, TM), 256, Y_SMEM>>>(p_f, p_g, p_yT, p_denom);

    // 7) yT *= 1/denom  (tf32-rounded)
    scale_yT_k<<<(NPIX * 128 + 255) / 256, 256>>>();

    // 8) out = w_out @ yT^T + b_out       [512, 9409]
    gemm_mma<1,0,0><<<dim3(TM, 4), 256, GEMM_SMEM>>>(
        p_woR, p_yT, out, CIN, NPIX, C2N, C2N, C2N, NPIX,
        b_out, nullptr, nullptr, 1.f, nullptr);
}